// round 17
// baseline (speedup 1.0000x reference)
#include <cuda_runtime.h>
#include <cuda_fp16.h>
#include <cstdint>
#include <cfloat>

#define DIM      128
#define KCODES   1024
#define TM       128
#define SUBN     32
#define NSUB     (KCODES / SUBN)
#define NTHREADS 256

// ---- smem byte offsets ----
#define SM_A      0        // 128 rows x 256B hi-only (swizzled)  = 32768
#define SM_B0     32768    // 32 rows x 256B                      = 8192
#define SM_B1     40960    //                                     = 8192
#define SM_E2     49152    // 1024 floats                         = 4096
#define SM_SD     53248    // 128 floats: per-row delta           = 512
#define SM_SM     53760    // 128 floats: per-row approx max      = 512
#define SM_REDV   54272    // 128*4 floats                        = 2048
#define SM_REDI   56320    // 128*4 ints                          = 2048
#define SM_CNT    58368    // 128 ints                            = 512
#define SM_CANDV  58880    // 128*16 floats                       = 8192
#define SM_CANDI  67072    // 128*16 ints                         = 8192
#define SM_FIDX   75264    // 128 ints                            = 512
#define SMEM_TOTAL 75776

__device__ float  g_e2[KCODES];
__device__ __half g_ehi[KCODES * DIM];   // fp16(embed), row-major
__device__ int    g_Zeh2i = 0;           // max_c ||eh_c||^2 (float bits, monotone)
__device__ int    g_Zel2i = 0;           // max_c ||el_c||^2

// ---------------------------------------------------------------- helpers
__device__ __forceinline__ uint32_t smem_u32(const void* p) {
    uint32_t a;
    asm("{ .reg .u64 t; cvta.to.shared.u64 t, %1; cvt.u32.u64 %0, t; }" : "=r"(a) : "l"(p));
    return a;
}
// 256B rows, 16B chunks XOR'd by row&7 -> conflict-free LDSM
__device__ __forceinline__ uint32_t sw256(int row, int ch) {
    return (uint32_t)(row * 256) + (uint32_t)(((ch ^ (row & 7)) << 4));
}
__device__ __forceinline__ void ldsm4(uint32_t* r, uint32_t a) {
    asm volatile("ldmatrix.sync.aligned.m8n8.x4.shared.b16 {%0,%1,%2,%3}, [%4];"
                 : "=r"(r[0]), "=r"(r[1]), "=r"(r[2]), "=r"(r[3]) : "r"(a));
}
__device__ __forceinline__ void mma16816(float* c, const uint32_t* a, uint32_t b0, uint32_t b1) {
    asm volatile("mma.sync.aligned.m16n8k16.row.col.f32.f16.f16.f32 "
                 "{%0,%1,%2,%3}, {%4,%5,%6,%7}, {%8,%9}, {%0,%1,%2,%3};"
                 : "+f"(c[0]), "+f"(c[1]), "+f"(c[2]), "+f"(c[3])
                 : "r"(a[0]), "r"(a[1]), "r"(a[2]), "r"(a[3]), "r"(b0), "r"(b1));
}
__device__ __forceinline__ void cp16(uint32_t dst, const void* src) {
    asm volatile("cp.async.cg.shared.global [%0], [%1], 16;"
                 :: "r"(dst), "l"(__cvta_generic_to_global(src)) : "memory");
}
__device__ __forceinline__ void cp_commit() { asm volatile("cp.async.commit_group;" ::: "memory"); }
__device__ __forceinline__ void cp_wait0()  { asm volatile("cp.async.wait_group 0;" ::: "memory"); }

// sorted top-4 insert; strict '>' keeps earliest (lowest-index) on ties
__device__ __forceinline__ void ins4(float v, int c, float* tv, int* ti) {
    if (v > tv[3]) {
        if (v > tv[2]) {
            tv[3] = tv[2]; ti[3] = ti[2];
            if (v > tv[1]) {
                tv[2] = tv[1]; ti[2] = ti[1];
                if (v > tv[0]) { tv[1] = tv[0]; ti[1] = ti[0]; tv[0] = v; ti[0] = c; }
                else           { tv[1] = v; ti[1] = c; }
            } else { tv[2] = v; ti[2] = c; }
        } else { tv[3] = v; ti[3] = c; }
    }
}

// ---------------------------------------------------------------- prep
// One warp per code: e2, fp16 hi, and global max hi/lo norms (atomicMax is
// monotone + idempotent -> deterministic across graph replays).
__global__ void prep_kernel(const float* __restrict__ embed) {
    int gw   = (blockIdx.x * blockDim.x + threadIdx.x) >> 5;
    int lane = threadIdx.x & 31;
    if (gw >= KCODES) return;
    float4 v = *(const float4*)(embed + (size_t)gw * DIM + lane * 4);
    __half h0 = __float2half_rn(v.x), h1 = __float2half_rn(v.y),
           h2 = __float2half_rn(v.z), h3 = __float2half_rn(v.w);
    float f0 = __half2float(h0), f1 = __half2float(h1),
          f2 = __half2float(h2), f3 = __half2float(h3);
    float l0 = v.x - f0, l1 = v.y - f1, l2 = v.z - f2, l3 = v.w - f3;

    float e2  = fmaf(v.x, v.x, fmaf(v.y, v.y, fmaf(v.z, v.z, v.w * v.w)));
    float eh2 = fmaf(f0, f0, fmaf(f1, f1, fmaf(f2, f2, f3 * f3)));
    float el2 = fmaf(l0, l0, fmaf(l1, l1, fmaf(l2, l2, l3 * l3)));
#pragma unroll
    for (int o = 16; o; o >>= 1) {
        e2  += __shfl_xor_sync(0xFFFFFFFFu, e2, o);
        eh2 += __shfl_xor_sync(0xFFFFFFFFu, eh2, o);
        el2 += __shfl_xor_sync(0xFFFFFFFFu, el2, o);
    }
    if (lane == 0) {
        g_e2[gw] = e2;
        atomicMax(&g_Zeh2i, __float_as_int(eh2));
        atomicMax(&g_Zel2i, __float_as_int(el2));
    }
    __half2 p01 = __halves2half2(h0, h1), p23 = __halves2half2(h2, h3);
    *(uint2*)(g_ehi + (size_t)gw * DIM + lane * 4) =
        make_uint2(*(uint32_t*)&p01, *(uint32_t*)&p23);
}

// ---------------------------------------------------------------- main
__global__ __launch_bounds__(NTHREADS, 2)
void vq_mma_kernel(const float* __restrict__ x, const float* __restrict__ embed,
                   float* __restrict__ out_q, float* __restrict__ out_idx, int nrows)
{
    extern __shared__ char smem[];
    const uint32_t sb = smem_u32(smem);
    const int tid = threadIdx.x;
    const int w   = tid >> 5;
    const int l   = tid & 31;
    const int rowbase = blockIdx.x * TM;

    // ---- prefetch B subtile 0 (eh only) ----
#pragma unroll
    for (int k = 0; k < 2; k++) {
        int id = tid + k * NTHREADS;           // 0..511 chunks (32 rows x 16)
        int r = id >> 4, ci = id & 15;
        cp16(sb + SM_B0 + sw256(r, ci), g_ehi + (size_t)r * DIM + ci * 8);
    }
    cp_commit();

    float* e2s = (float*)(smem + SM_E2);
    for (int i = tid; i < KCODES; i += NTHREADS) e2s[i] = g_e2[i];

    // ---- A prologue: one row per thread (tid<128): hi into smem + row norms
    float* sDelta = (float*)(smem + SM_SD);
    if (tid < TM) {
        int rg = rowbase + tid; if (rg >= nrows) rg = nrows - 1;
        const float* xp = x + (size_t)rg * DIM;
        float xh2 = 0.f, xl2 = 0.f;
#pragma unroll 4
        for (int ch = 0; ch < 16; ch++) {
            float4 a = *(const float4*)(xp + ch * 8);
            float4 b = *(const float4*)(xp + ch * 8 + 4);
            __half h0 = __float2half_rn(a.x), h1 = __float2half_rn(a.y),
                   h2 = __float2half_rn(a.z), h3 = __float2half_rn(a.w),
                   h4 = __float2half_rn(b.x), h5 = __float2half_rn(b.y),
                   h6 = __float2half_rn(b.z), h7 = __float2half_rn(b.w);
            float f0 = __half2float(h0), f1 = __half2float(h1), f2 = __half2float(h2),
                  f3 = __half2float(h3), f4 = __half2float(h4), f5 = __half2float(h5),
                  f6 = __half2float(h6), f7 = __half2float(h7);
            xh2 += f0*f0 + f1*f1 + f2*f2 + f3*f3 + f4*f4 + f5*f5 + f6*f6 + f7*f7;
            float r0 = a.x-f0, r1 = a.y-f1, r2 = a.z-f2, r3 = a.w-f3,
                  r4 = b.x-f4, r5 = b.y-f5, r6 = b.z-f6, r7 = b.w-f7;
            xl2 += r0*r0 + r1*r1 + r2*r2 + r3*r3 + r4*r4 + r5*r5 + r6*r6 + r7*r7;
            __half2 p01 = __halves2half2(h0, h1), p23 = __halves2half2(h2, h3),
                    p45 = __halves2half2(h4, h5), p67 = __halves2half2(h6, h7);
            *(uint4*)(smem + SM_A + sw256(tid, ch)) =
                make_uint4(*(uint32_t*)&p01, *(uint32_t*)&p23,
                           *(uint32_t*)&p45, *(uint32_t*)&p67);
        }
        // deterministic Cauchy-Schwarz bound on dropped terms (2S scale)
        float Zeh = sqrtf(__int_as_float(g_Zeh2i));
        float Zel = sqrtf(__int_as_float(g_Zel2i));
        float nxh = sqrtf(xh2), nxl = sqrtf(xl2);
        sDelta[tid] = 2.0f * (nxl * Zeh + nxh * Zel + nxl * Zel) * 1.02f + 1e-3f;
    }
    __syncthreads();   // A visible

    // per-warp geometry: 16 rows x 32 cols
    const int mrow0 = w * 16;
    const int ag    = l >> 4;
    const int brow0 = ((l >> 4) << 3) + (l & 7);
    const int bg    = (l >> 3) & 1;

    // hoist A-hi fragments (constant across all 32 subtiles): 8 ldsm4 = 32 regs
    uint32_t aH[8][4];
#pragma unroll
    for (int kt = 0; kt < 8; kt++)
        ldsm4(aH[kt], sb + SM_A + sw256(mrow0 + (l & 15), kt * 2 + ag));

    // per-thread top-4 for each of 2 row-slots
    float tv[2][4]; int ti[2][4];
#pragma unroll
    for (int s2 = 0; s2 < 2; s2++)
#pragma unroll
        for (int k = 0; k < 4; k++) { tv[s2][k] = -FLT_MAX; ti[s2][k] = 0; }

    for (int s = 0; s < NSUB; s++) {
        cp_wait0();
        __syncthreads();   // publish buf s; certifies compute s-1 done

        if (s + 1 < NSUB) {
            const uint32_t bn = sb + (((s + 1) & 1) ? SM_B1 : SM_B0);
#pragma unroll
            for (int k = 0; k < 2; k++) {
                int id = tid + k * NTHREADS;
                int r = id >> 4, ci = id & 15;
                cp16(bn + sw256(r, ci),
                     g_ehi + ((size_t)(s + 1) * SUBN + r) * DIM + ci * 8);
            }
            cp_commit();
        }

        const uint32_t bbase = sb + ((s & 1) ? SM_B1 : SM_B0);

        float c[4][4];
#pragma unroll
        for (int j = 0; j < 4; j++)
#pragma unroll
            for (int i = 0; i < 4; i++) c[j][i] = 0.f;

#pragma unroll
        for (int kt = 0; kt < 8; kt++) {
            uint32_t b0[4], b1[4];
            const int ck = kt * 2;
            ldsm4(b0, bbase + sw256(brow0,      ck + bg));   // codes 0-15
            ldsm4(b1, bbase + sw256(brow0 + 16, ck + bg));   // codes 16-31
            mma16816(c[0], aH[kt], b0[0], b0[1]);
            mma16816(c[1], aH[kt], b0[2], b0[3]);
            mma16816(c[2], aH[kt], b1[0], b1[1]);
            mma16816(c[3], aH[kt], b1[2], b1[3]);
        }

        // score + per-slot top-4 (ascending code order within thread)
#pragma unroll
        for (int j = 0; j < 4; j++) {
            int col0 = s * SUBN + j * 8 + (l & 3) * 2;
            float2 e = *(const float2*)(e2s + col0);
            float v0 = fmaf(2.f, c[j][0], -e.x);
            float v1 = fmaf(2.f, c[j][1], -e.y);
            float v2 = fmaf(2.f, c[j][2], -e.x);
            float v3 = fmaf(2.f, c[j][3], -e.y);
            ins4(v0, col0,     tv[0], ti[0]);
            ins4(v1, col0 + 1, tv[0], ti[0]);
            ins4(v2, col0,     tv[1], ti[1]);
            ins4(v3, col0 + 1, tv[1], ti[1]);
        }
    }
    __syncthreads();

    // ---- Phase A: publish per-slot top-1 (4 lane-quarters per row) ----
    float* redv = (float*)(smem + SM_REDV);
    int*   redi = (int*)(smem + SM_REDI);
    {
        int ra = mrow0 + (l >> 2), cd = l & 3;
        redv[ra * 4 + cd]       = tv[0][0]; redi[ra * 4 + cd]       = ti[0][0];
        redv[(ra + 8) * 4 + cd] = tv[1][0]; redi[(ra + 8) * 4 + cd] = ti[1][0];
    }
    __syncthreads();

    // ---- Phase B: per-row approx max + init candidate counters ----
    float* sM   = (float*)(smem + SM_SM);
    int*   nCnt = (int*)(smem + SM_CNT);
    int*   fIdx = (int*)(smem + SM_FIDX);
    if (tid < TM) {
        float bv = redv[tid * 4]; int bi = redi[tid * 4];
#pragma unroll
        for (int cd = 1; cd < 4; cd++) {
            float v = redv[tid * 4 + cd]; int ii = redi[tid * 4 + cd];
            if (v > bv || (v == bv && ii < bi)) { bv = v; bi = ii; }
        }
        sM[tid] = bv; fIdx[tid] = bi; nCnt[tid] = 0;
    }
    __syncthreads();

    // ---- Phase C: append all candidates within the certified window ----
    float* candv = (float*)(smem + SM_CANDV);
    int*   candi = (int*)(smem + SM_CANDI);
#pragma unroll
    for (int s2 = 0; s2 < 2; s2++) {
        int row = mrow0 + (l >> 2) + s2 * 8;
        float thr = sM[row] - 2.0f * sDelta[row];
#pragma unroll
        for (int k = 0; k < 4; k++) {
            if (tv[s2][k] >= thr) {
                int pos = atomicAdd(&nCnt[row], 1);
                if (pos < 16) {
                    candv[row * 16 + pos] = tv[s2][k];
                    candi[row * 16 + pos] = ti[s2][k];
                }
            }
        }
    }
    __syncthreads();

    // ---- Phase D: exact fp64 rescore where >1 candidate survives ----
    if (tid < TM) {
        int r = tid, n = nCnt[r];
        if (n > 1) {
            int rg = rowbase + r; if (rg >= nrows) rg = nrows - 1;
            const float* xr = x + (size_t)rg * DIM;
            double bestd = -1e300; int bidx = 1 << 30;
            int m = (n <= 16) ? n : KCODES;
            for (int k = 0; k < m; k++) {
                int idx = (n <= 16) ? candi[r * 16 + k] : k;
                const float* er = embed + (size_t)idx * DIM;
                double d0 = 0, d1 = 0, d2 = 0, d3 = 0;
                double s0 = 0, s1 = 0, s2 = 0, s3 = 0;
#pragma unroll 8
                for (int i = 0; i < DIM; i += 4) {
                    double e0 = er[i], e1 = er[i+1], e2v = er[i+2], e3 = er[i+3];
                    d0 = fma((double)xr[i],   e0,  d0);
                    d1 = fma((double)xr[i+1], e1,  d1);
                    d2 = fma((double)xr[i+2], e2v, d2);
                    d3 = fma((double)xr[i+3], e3,  d3);
                    s0 = fma(e0, e0, s0); s1 = fma(e1, e1, s1);
                    s2 = fma(e2v, e2v, s2); s3 = fma(e3, e3, s3);
                }
                double val = 2.0 * ((d0 + d1) + (d2 + d3)) - ((s0 + s1) + (s2 + s3));
                if (val > bestd || (val == bestd && idx < bidx)) { bestd = val; bidx = idx; }
            }
            fIdx[r] = bidx;
        }
        int rg = rowbase + r;
        if (out_idx != nullptr && rg < nrows) out_idx[rg] = (float)fIdx[r];
    }
    __syncthreads();

    // ---- gather: quantize = embed[idx] (bitwise-exact fp32 copy) ----
    for (int i = tid; i < TM * (DIM / 4); i += NTHREADS) {
        int r = i >> 5, c4 = (i & 31) << 2;
        int rg = rowbase + r;
        if (rg < nrows) {
            float4 v = *(const float4*)(embed + (size_t)fIdx[r] * DIM + c4);
            *(float4*)(out_q + (size_t)rg * DIM + c4) = v;
        }
    }
}

__global__ void fill_kernel(float* p, long long n) {
    long long i = (long long)blockIdx.x * blockDim.x + threadIdx.x;
    if (i < n) p[i] = 0.f;
}

// ---------------------------------------------------------------- launch
extern "C" void kernel_launch(void* const* d_in, const int* in_sizes, int n_in,
                              void* d_out, int out_size) {
    int xi = 0, ei = 1;
    if (n_in >= 2 && in_sizes[1] > in_sizes[0]) { xi = 1; ei = 0; }
    const float* x     = (const float*)d_in[xi];
    const float* embed = (const float*)d_in[ei];
    int nrows = in_sizes[xi] / DIM;

    float* out_q = (float*)d_out;
    long long ND = (long long)nrows * DIM;
    bool widx = ((long long)out_size >= ND + nrows);
    float* out_idx = widx ? out_q + ND : nullptr;

    prep_kernel<<<(KCODES * 32 + 255) / 256, 256>>>(embed);

    cudaFuncSetAttribute(vq_mma_kernel, cudaFuncAttributeMaxDynamicSharedMemorySize, SMEM_TOTAL);
    vq_mma_kernel<<<(nrows + TM - 1) / TM, NTHREADS, SMEM_TOTAL>>>(x, embed, out_q, out_idx, nrows);

    long long covered = ND + (widx ? nrows : 0);
    long long tail = (long long)out_size - covered;
    if (tail > 0)
        fill_kernel<<<(int)((tail + 255) / 256), 256>>>(out_q + covered, tail);
}